// round 6
// baseline (speedup 1.0000x reference)
#include <cuda_runtime.h>
#include <cuda_bf16.h>
#include <cstdint>

// ============================================================================
// sim = clamp(xn @ xn.T, 0), xn = row-normalized features (8192 x 256 fp32)
//
// sm_100 (no 'a') -> mma.sync.m16n8k16 bf16 + cp.async + ldmatrix.
// bf16 split, symmetric K-tripling: A=[hi|lo|hi], B=[hi|hi|lo] (K=768).
// CTA tile 256x128 (8 warps, 64x64 each), 3-stage cp.async pipeline.
// Triangle-only tiles (1056) + mirrored write via smem transpose.
// ============================================================================

#define NROWS  8192
#define DIM    256
#define KCH    64            // bf16 per K-chunk (128 B rows)
#define NCHUNK 12            // virtual K = 768
#define TM     256           // CTA tile M
#define TN     128           // CTA tile N

__device__ __align__(128) __nv_bfloat16 g_X[(size_t)NROWS * 512];

// ---------------------------------------------------------------------------
__device__ __forceinline__ uint32_t smem_u32(const void* p) {
    uint32_t a;
    asm("{ .reg .u64 t; cvta.to.shared.u64 t, %1; cvt.u32.u64 %0, t; }"
        : "=r"(a) : "l"(p));
    return a;
}

#define CP_ASYNC_16(dst, src) \
    asm volatile("cp.async.cg.shared.global [%0], [%1], 16;" \
                 :: "r"(dst), "l"(src) : "memory")
#define CP_ASYNC_COMMIT() \
    asm volatile("cp.async.commit_group;" ::: "memory")
#define CP_ASYNC_WAIT(n) \
    asm volatile("cp.async.wait_group %0;" :: "n"(n) : "memory")

__device__ __forceinline__ void ldsm4(uint32_t* r, uint32_t addr) {
    asm volatile("ldmatrix.sync.aligned.m8n8.x4.shared.b16 {%0,%1,%2,%3}, [%4];"
                 : "=r"(r[0]), "=r"(r[1]), "=r"(r[2]), "=r"(r[3]) : "r"(addr));
}

__device__ __forceinline__ void mma16816(float* d, const uint32_t* a,
                                         const uint32_t* b) {
    asm volatile(
        "mma.sync.aligned.m16n8k16.row.col.f32.bf16.bf16.f32 "
        "{%0,%1,%2,%3}, {%4,%5,%6,%7}, {%8,%9}, {%0,%1,%2,%3};"
        : "+f"(d[0]), "+f"(d[1]), "+f"(d[2]), "+f"(d[3])
        : "r"(a[0]), "r"(a[1]), "r"(a[2]), "r"(a[3]), "r"(b[0]), "r"(b[1]));
}

// ---------------------------------------------------------------------------
// Kernel 1: normalize rows, emit bf16 split [hi | lo].
// ---------------------------------------------------------------------------
__global__ void __launch_bounds__(256)
norm_split_kernel(const float* __restrict__ feats)
{
    const int row  = blockIdx.x * 8 + (threadIdx.x >> 5);
    const int lane = threadIdx.x & 31;

    const float4* src = reinterpret_cast<const float4*>(feats + (size_t)row * DIM);
    float4 v0 = src[lane * 2];
    float4 v1 = src[lane * 2 + 1];

    float ss = v0.x * v0.x + v0.y * v0.y + v0.z * v0.z + v0.w * v0.w
             + v1.x * v1.x + v1.y * v1.y + v1.z * v1.z + v1.w * v1.w;
    #pragma unroll
    for (int o = 16; o; o >>= 1)
        ss += __shfl_xor_sync(0xFFFFFFFFu, ss, o);

    const float inv = 1.0f / fmaxf(sqrtf(ss), 1e-8f);

    float vals[8] = {v0.x, v0.y, v0.z, v0.w, v1.x, v1.y, v1.z, v1.w};
    const size_t base = (size_t)row * 512;
    #pragma unroll
    for (int j = 0; j < 8; ++j) {
        const int c = lane * 8 + j;
        float xn = vals[j] * inv;
        __nv_bfloat16 hi = __float2bfloat16(xn);
        __nv_bfloat16 lo = __float2bfloat16(xn - __bfloat162float(hi));
        g_X[base + c]       = hi;
        g_X[base + 256 + c] = lo;
    }
}

// ---------------------------------------------------------------------------
// Kernel 2: 256x128 CTA tile, 8 warps (64x64 each, 4x2 grid), 3 stages.
// smem per stage: A 256x128B = 32 KB, B 128x128B = 16 KB  -> 48 KB
// Epilogue mirror buffer: float[256][129] = 132096 B (reuses stage smem).
// ---------------------------------------------------------------------------
#define SMEM_STAGE_SZ 49152
#define SMEM_B_OFF    32768          // within a stage
#define SMEM_TOTAL    147456         // 3 stages; >= 132096 mirror buffer

__global__ void __launch_bounds__(256)
cosine_gemm_kernel(float* __restrict__ out)
{
    extern __shared__ char smem[];
    const uint32_t sbase = smem_u32(smem);
    const int tid  = threadIdx.x;
    const int lane = tid & 31;
    const int wid  = tid >> 5;

    // Tile decode: tiles per stripe by = 2*by+2 ; cumulative = by*(by+1)
    const int t = blockIdx.x;
    int by = (int)((sqrtf(4.0f * (float)t + 1.0f) - 1.0f) * 0.5f);
    while ((by + 1) * (by + 2) <= t) ++by;
    while (by * (by + 1) > t) --by;
    const int bx = t - by * (by + 1);

    const int rowbase = by * TM;     // M rows (A operand)
    const int colbase = bx * TN;     // N cols (B operand)

    const int wm = (wid >> 1) * 64;  // warp tile origin in M (0,64,128,192)
    const int wn = (wid & 1) * 64;   // warp tile origin in N (0,64)

    // --- cp.async loader: A 8 groups + B 4 groups of 16B per thread ------
    const int lr = tid >> 3;         // 0..31
    const int lc = tid & 7;          // 0..7

    auto issue = [&](int kc) {
        const int ka = (kc < 8) ? kc : kc - 8;   // A: [hi | lo | hi]
        const int kb = (kc < 4) ? kc : kc - 4;   // B: [hi | hi | lo]
        const uint32_t stg = (uint32_t)(kc % 3) * SMEM_STAGE_SZ;
        #pragma unroll
        for (int p = 0; p < 8; ++p) {
            const int row = p * 32 + lr;
            const uint32_t swc = (uint32_t)((lc ^ (row & 7)) * 16);
            CP_ASYNC_16(sbase + stg + row * 128 + swc,
                &g_X[(size_t)(rowbase + row) * 512 + ka * KCH + lc * 8]);
        }
        #pragma unroll
        for (int p = 0; p < 4; ++p) {
            const int row = p * 32 + lr;
            const uint32_t swc = (uint32_t)((lc ^ (row & 7)) * 16);
            CP_ASYNC_16(sbase + stg + SMEM_B_OFF + row * 128 + swc,
                &g_X[(size_t)(colbase + row) * 512 + kb * KCH + lc * 8]);
        }
        CP_ASYNC_COMMIT();
    };

    float acc[4][8][4];
    #pragma unroll
    for (int i = 0; i < 4; ++i)
        #pragma unroll
        for (int j = 0; j < 8; ++j)
            #pragma unroll
            for (int r = 0; r < 4; ++r)
                acc[i][j][r] = 0.0f;

    issue(0);
    issue(1);

    for (int kc = 0; kc < NCHUNK; ++kc) {
        if (kc == NCHUNK - 1) { CP_ASYNC_WAIT(0); } else { CP_ASYNC_WAIT(1); }
        __syncthreads();

        const uint32_t aB = sbase + (uint32_t)(kc % 3) * SMEM_STAGE_SZ;
        const uint32_t bB = aB + SMEM_B_OFF;

        #pragma unroll
        for (int s = 0; s < 4; ++s) {            // 4 x K16 per chunk
            uint32_t afr[4][4];
            #pragma unroll
            for (int i = 0; i < 4; ++i) {
                const int row = wm + 16 * i + (lane & 15);
                const int ch  = s * 2 + (lane >> 4);
                ldsm4(afr[i], aB + row * 128 + ((ch ^ (row & 7)) * 16));
            }
            uint32_t bfr[4][4];
            #pragma unroll
            for (int jj = 0; jj < 4; ++jj) {
                const int row = wn + 16 * jj + ((lane >> 4) << 3) + (lane & 7);
                const int ch  = s * 2 + ((lane >> 3) & 1);
                ldsm4(bfr[jj], bB + row * 128 + ((ch ^ (row & 7)) * 16));
            }
            #pragma unroll
            for (int i = 0; i < 4; ++i)
                #pragma unroll
                for (int j = 0; j < 8; ++j)
                    mma16816(acc[i][j], afr[i], &bfr[j >> 1][(j & 1) * 2]);
        }
        __syncthreads();
        if (kc + 2 < NCHUNK) issue(kc + 2);
    }

    // --- Epilogue ---------------------------------------------------------
    const int grp = lane >> 2;       // 0..7
    const int t4  = lane & 3;        // 0..3

    // Direct write (full tile; straddle tiles are correct by symmetry).
    #pragma unroll
    for (int i = 0; i < 4; ++i) {
        #pragma unroll
        for (int j = 0; j < 8; ++j) {
            const size_t gr = (size_t)(rowbase + wm + 16 * i + grp);
            const size_t gc = (size_t)(colbase + wn + 8 * j + t4 * 2);
            float2 v01 = make_float2(fmaxf(acc[i][j][0], 0.0f),
                                     fmaxf(acc[i][j][1], 0.0f));
            float2 v23 = make_float2(fmaxf(acc[i][j][2], 0.0f),
                                     fmaxf(acc[i][j][3], 0.0f));
            *reinterpret_cast<float2*>(&out[gr * NROWS + gc]) = v01;
            *reinterpret_cast<float2*>(&out[(gr + 8) * NROWS + gc]) = v23;
        }
    }

    // Mirror write via smem transpose. All writes are consistent duplicates
    // where regions overlap (symmetric values), so no conditionals needed.
    {
        float* ctile = reinterpret_cast<float*>(smem);   // [256][129]
        __syncthreads();   // all mainloop smem reads complete
        #pragma unroll
        for (int i = 0; i < 4; ++i) {
            #pragma unroll
            for (int j = 0; j < 8; ++j) {
                const int m = wm + 16 * i + grp;
                const int n = wn + 8 * j + t4 * 2;
                ctile[m * 129 + n]           = fmaxf(acc[i][j][0], 0.0f);
                ctile[m * 129 + n + 1]       = fmaxf(acc[i][j][1], 0.0f);
                ctile[(m + 8) * 129 + n]     = fmaxf(acc[i][j][2], 0.0f);
                ctile[(m + 8) * 129 + n + 1] = fmaxf(acc[i][j][3], 0.0f);
            }
        }
        __syncthreads();
        // warp w: n = w*16 .. w*16+15 ; column reads conflict-free (129 odd)
        #pragma unroll
        for (int rr = 0; rr < 16; ++rr) {
            const int n = wid * 16 + rr;
            #pragma unroll
            for (int q = 0; q < 8; ++q) {
                const int m = q * 32 + lane;
                out[(size_t)(colbase + n) * NROWS + rowbase + m] =
                    ctile[m * 129 + n];
            }
        }
    }
}

// ---------------------------------------------------------------------------
extern "C" void kernel_launch(void* const* d_in, const int* in_sizes, int n_in,
                              void* d_out, int out_size)
{
    const float* feats = (const float*)d_in[0];
    float* out = (float*)d_out;
    (void)in_sizes; (void)n_in; (void)out_size;

    cudaFuncSetAttribute(cosine_gemm_kernel,
                         cudaFuncAttributeMaxDynamicSharedMemorySize,
                         SMEM_TOTAL);

    norm_split_kernel<<<NROWS / 8, 256>>>(feats);

    const int nstripes = NROWS / TM;                       // 32
    const int ntiles = nstripes * (nstripes + 1);          // 1056
    cosine_gemm_kernel<<<ntiles, 256, SMEM_TOTAL>>>(out);
}

// round 7
// speedup vs baseline: 1.2317x; 1.2317x over previous
#include <cuda_runtime.h>
#include <cuda_bf16.h>
#include <cstdint>

// ============================================================================
// sim = clamp(xn @ xn.T, 0), xn = row-normalized features (8192 x 256 fp32)
//
// sm_100 (no 'a') -> mma.sync.m16n8k16 bf16 + cp.async + ldmatrix.
// bf16 split, symmetric K-tripling: A=[hi|lo|hi], B=[hi|hi|lo] (K=768).
// R7: CTA tile 128x128 with FOUR warps (64x64 each) -> per-warp efficiency of
// R6 (LDSM:MMA = 1:4) with 2 CTAs/SM co-residency of R3 (barrier/epilogue
// overlap). 3-stage cp.async. Triangle tiles (2080) + mirror via transpose.
// ============================================================================

#define NROWS  8192
#define DIM    256
#define KCH    64            // bf16 per K-chunk (128 B rows)
#define NCHUNK 12            // virtual K = 768
#define TILE   128

__device__ __align__(128) __nv_bfloat16 g_X[(size_t)NROWS * 512];

// ---------------------------------------------------------------------------
__device__ __forceinline__ uint32_t smem_u32(const void* p) {
    uint32_t a;
    asm("{ .reg .u64 t; cvta.to.shared.u64 t, %1; cvt.u32.u64 %0, t; }"
        : "=r"(a) : "l"(p));
    return a;
}

#define CP_ASYNC_16(dst, src) \
    asm volatile("cp.async.cg.shared.global [%0], [%1], 16;" \
                 :: "r"(dst), "l"(src) : "memory")
#define CP_ASYNC_COMMIT() \
    asm volatile("cp.async.commit_group;" ::: "memory")
#define CP_ASYNC_WAIT(n) \
    asm volatile("cp.async.wait_group %0;" :: "n"(n) : "memory")

__device__ __forceinline__ void ldsm4(uint32_t* r, uint32_t addr) {
    asm volatile("ldmatrix.sync.aligned.m8n8.x4.shared.b16 {%0,%1,%2,%3}, [%4];"
                 : "=r"(r[0]), "=r"(r[1]), "=r"(r[2]), "=r"(r[3]) : "r"(addr));
}

__device__ __forceinline__ void mma16816(float* d, const uint32_t* a,
                                         const uint32_t* b) {
    asm volatile(
        "mma.sync.aligned.m16n8k16.row.col.f32.bf16.bf16.f32 "
        "{%0,%1,%2,%3}, {%4,%5,%6,%7}, {%8,%9}, {%0,%1,%2,%3};"
        : "+f"(d[0]), "+f"(d[1]), "+f"(d[2]), "+f"(d[3])
        : "r"(a[0]), "r"(a[1]), "r"(a[2]), "r"(a[3]), "r"(b[0]), "r"(b[1]));
}

// ---------------------------------------------------------------------------
// Kernel 1: normalize rows, emit bf16 split [hi | lo].
// ---------------------------------------------------------------------------
__global__ void __launch_bounds__(256)
norm_split_kernel(const float* __restrict__ feats)
{
    const int row  = blockIdx.x * 8 + (threadIdx.x >> 5);
    const int lane = threadIdx.x & 31;

    const float4* src = reinterpret_cast<const float4*>(feats + (size_t)row * DIM);
    float4 v0 = src[lane * 2];
    float4 v1 = src[lane * 2 + 1];

    float ss = v0.x * v0.x + v0.y * v0.y + v0.z * v0.z + v0.w * v0.w
             + v1.x * v1.x + v1.y * v1.y + v1.z * v1.z + v1.w * v1.w;
    #pragma unroll
    for (int o = 16; o; o >>= 1)
        ss += __shfl_xor_sync(0xFFFFFFFFu, ss, o);

    const float inv = 1.0f / fmaxf(sqrtf(ss), 1e-8f);

    float vals[8] = {v0.x, v0.y, v0.z, v0.w, v1.x, v1.y, v1.z, v1.w};
    const size_t base = (size_t)row * 512;
    #pragma unroll
    for (int j = 0; j < 8; ++j) {
        const int c = lane * 8 + j;
        float xn = vals[j] * inv;
        __nv_bfloat16 hi = __float2bfloat16(xn);
        __nv_bfloat16 lo = __float2bfloat16(xn - __bfloat162float(hi));
        g_X[base + c]       = hi;
        g_X[base + 256 + c] = lo;
    }
}

// ---------------------------------------------------------------------------
// Kernel 2: 128x128 CTA tile, 4 warps (64x64 each, 2x2), 3 stages, 128 thr.
// smem per stage: A 128x128B = 16 KB + B 16 KB -> 32 KB; x3 = 96 KB.
// Mirror buffer: float[128][129] = 66048 B (reuses stage smem).
// 2 CTAs/SM (2*96 KB = 192 KB <= 228 KB).
// ---------------------------------------------------------------------------
#define SMEM_STAGE_SZ 32768
#define SMEM_B_OFF    16384          // within a stage
#define SMEM_TOTAL    98304          // 3 stages; >= 66048 mirror buffer

__global__ void __launch_bounds__(128)
cosine_gemm_kernel(float* __restrict__ out)
{
    extern __shared__ char smem[];
    const uint32_t sbase = smem_u32(smem);
    const int tid  = threadIdx.x;
    const int lane = tid & 31;
    const int wid  = tid >> 5;       // 0..3

    // Triangular tile decode: t -> (by, bx), bx <= by
    const int t = blockIdx.x;
    int by = (int)((sqrtf(8.0f * (float)t + 1.0f) - 1.0f) * 0.5f);
    while ((by + 1) * (by + 2) / 2 <= t) ++by;
    while (by * (by + 1) / 2 > t) --by;
    const int bx = t - by * (by + 1) / 2;

    const int rowbase = by * TILE;   // M rows (A operand)
    const int colbase = bx * TILE;   // N cols (B operand)

    const int wm = (wid >> 1) * 64;  // warp tile origin in M (0, 64)
    const int wn = (wid & 1) * 64;   // warp tile origin in N (0, 64)

    // --- cp.async loader: A 8 + B 8 groups of 16B per thread -------------
    const int lr = tid >> 3;         // 0..15
    const int lc = tid & 7;          // 0..7

    auto issue = [&](int kc) {
        const int ka = (kc < 8) ? kc : kc - 8;   // A: [hi | lo | hi]
        const int kb = (kc < 4) ? kc : kc - 4;   // B: [hi | hi | lo]
        const uint32_t stg = (uint32_t)(kc % 3) * SMEM_STAGE_SZ;
        #pragma unroll
        for (int p = 0; p < 8; ++p) {
            const int row = p * 16 + lr;
            const uint32_t swc = (uint32_t)((lc ^ (row & 7)) * 16);
            CP_ASYNC_16(sbase + stg + row * 128 + swc,
                &g_X[(size_t)(rowbase + row) * 512 + ka * KCH + lc * 8]);
            CP_ASYNC_16(sbase + stg + SMEM_B_OFF + row * 128 + swc,
                &g_X[(size_t)(colbase + row) * 512 + kb * KCH + lc * 8]);
        }
        CP_ASYNC_COMMIT();
    };

    float acc[4][8][4];
    #pragma unroll
    for (int i = 0; i < 4; ++i)
        #pragma unroll
        for (int j = 0; j < 8; ++j)
            #pragma unroll
            for (int r = 0; r < 4; ++r)
                acc[i][j][r] = 0.0f;

    issue(0);
    issue(1);

    for (int kc = 0; kc < NCHUNK; ++kc) {
        if (kc == NCHUNK - 1) { CP_ASYNC_WAIT(0); } else { CP_ASYNC_WAIT(1); }
        __syncthreads();

        const uint32_t aB = sbase + (uint32_t)(kc % 3) * SMEM_STAGE_SZ;
        const uint32_t bB = aB + SMEM_B_OFF;

        #pragma unroll
        for (int s = 0; s < 4; ++s) {            // 4 x K16 per chunk
            uint32_t afr[4][4];
            #pragma unroll
            for (int i = 0; i < 4; ++i) {
                const int row = wm + 16 * i + (lane & 15);
                const int ch  = s * 2 + (lane >> 4);
                ldsm4(afr[i], aB + row * 128 + ((ch ^ (row & 7)) * 16));
            }
            uint32_t bfr[4][4];
            #pragma unroll
            for (int jj = 0; jj < 4; ++jj) {
                const int row = wn + 16 * jj + ((lane >> 4) << 3) + (lane & 7);
                const int ch  = s * 2 + ((lane >> 3) & 1);
                ldsm4(bfr[jj], bB + row * 128 + ((ch ^ (row & 7)) * 16));
            }
            #pragma unroll
            for (int i = 0; i < 4; ++i)
                #pragma unroll
                for (int j = 0; j < 8; ++j)
                    mma16816(acc[i][j], afr[i], &bfr[j >> 1][(j & 1) * 2]);
        }
        __syncthreads();
        if (kc + 2 < NCHUNK) issue(kc + 2);
    }

    // --- Epilogue ---------------------------------------------------------
    const int grp = lane >> 2;       // 0..7
    const int t4  = lane & 3;        // 0..3

    // Direct write from registers (float2 = full 32B sector per quad).
    #pragma unroll
    for (int i = 0; i < 4; ++i) {
        #pragma unroll
        for (int j = 0; j < 8; ++j) {
            const size_t gr = (size_t)(rowbase + wm + 16 * i + grp);
            const size_t gc = (size_t)(colbase + wn + 8 * j + t4 * 2);
            float2 v01 = make_float2(fmaxf(acc[i][j][0], 0.0f),
                                     fmaxf(acc[i][j][1], 0.0f));
            float2 v23 = make_float2(fmaxf(acc[i][j][2], 0.0f),
                                     fmaxf(acc[i][j][3], 0.0f));
            *reinterpret_cast<float2*>(&out[gr * NROWS + gc]) = v01;
            *reinterpret_cast<float2*>(&out[(gr + 8) * NROWS + gc]) = v23;
        }
    }

    // Mirror write via smem transpose (skip on diagonal tiles).
    if (bx != by) {
        float* ctile = reinterpret_cast<float*>(smem);   // [128][129]
        __syncthreads();   // mainloop smem reads complete
        #pragma unroll
        for (int i = 0; i < 4; ++i) {
            #pragma unroll
            for (int j = 0; j < 8; ++j) {
                const int m = wm + 16 * i + grp;
                const int n = wn + 8 * j + t4 * 2;
                ctile[m * 129 + n]           = fmaxf(acc[i][j][0], 0.0f);
                ctile[m * 129 + n + 1]       = fmaxf(acc[i][j][1], 0.0f);
                ctile[(m + 8) * 129 + n]     = fmaxf(acc[i][j][2], 0.0f);
                ctile[(m + 8) * 129 + n + 1] = fmaxf(acc[i][j][3], 0.0f);
            }
        }
        __syncthreads();
        // warp w: n = w*32 .. w*32+31 ; stride-129 column reads conflict-free
        #pragma unroll
        for (int rr = 0; rr < 32; ++rr) {
            const int n = wid * 32 + rr;
            #pragma unroll
            for (int q = 0; q < 4; ++q) {
                const int m = q * 32 + lane;
                out[(size_t)(colbase + n) * NROWS + rowbase + m] =
                    ctile[m * 129 + n];
            }
        }
    }
}

// ---------------------------------------------------------------------------
extern "C" void kernel_launch(void* const* d_in, const int* in_sizes, int n_in,
                              void* d_out, int out_size)
{
    const float* feats = (const float*)d_in[0];
    float* out = (float*)d_out;
    (void)in_sizes; (void)n_in; (void)out_size;

    cudaFuncSetAttribute(cosine_gemm_kernel,
                         cudaFuncAttributeMaxDynamicSharedMemorySize,
                         SMEM_TOTAL);

    norm_split_kernel<<<NROWS / 8, 256>>>(feats);

    const int ntiles = (NROWS / TILE) * (NROWS / TILE + 1) / 2;   // 2080
    cosine_gemm_kernel<<<ntiles, 128, SMEM_TOTAL>>>(out);
}